// round 1
// baseline (speedup 1.0000x reference)
#include <cuda_runtime.h>

// PointTransformerLayer: B=1, N=1024, D=64, H_POS=64, H_ATTN=256
// Strategy:
//   proj_kernel: q,k,v = x@W*, a = pos@pW1   (tiny, precomputed to __device__ globals)
//   pt_main: one CTA per query i. Stream j in tiles of 32:
//     ph  = relu(a_i - a_j + pb1)                [32,64]
//     rpe = ph @ pW2 + pb2 ; u = q_i - k_j + rpe ; vv = v_j + rpe
//     H   = relu(u @ aW1 + ab1)                  [32,256]
//     S   = H @ aW2 + ab2                        [32,64]
//     per-channel online softmax over j (per-thread partials, merged at end)
//   All GEMMs use packed fma.rn.f32x2 (FFMA2) for 2x fp32 rate on sm_103a.

#define NTOK 1024
#define DIM 64
#define HATT 256
#define TJ 32

// smem layout (float offsets)
#define OFF_AW1 0        // 64*256
#define OFF_AW2 16384    // 256*64
#define OFF_PW2 32768    // 64*64
#define OFF_H   36864    // 32*256 (first 32*64 aliased as sPh before GEMM1)
#define OFF_U   45056    // 32*64
#define OFF_VV  47104    // 32*64
#define OFF_S   49152    // 32*64
#define OFF_QI  51200    // 64
#define OFF_AI  51264    // 64
#define OFF_AB1 51328    // 256
#define OFF_AB2 51584    // 64
#define OFF_PB1 51648    // 64
#define OFF_PB2 51712    // 64
#define OFF_RED 51776    // 3*256
#define SMEM_FLOATS 52544
#define SMEM_BYTES (SMEM_FLOATS * 4)

__device__ float g_q[NTOK * DIM];
__device__ float g_k[NTOK * DIM];
__device__ float g_v[NTOK * DIM];
__device__ float g_a[NTOK * DIM];

typedef unsigned long long u64;

__device__ __forceinline__ u64 bcast2(float a) {
    u64 r; asm("mov.b64 %0, {%1,%1};" : "=l"(r) : "f"(a)); return r;
}
__device__ __forceinline__ void fma2(u64 &d, u64 a, u64 b) {
    asm("fma.rn.f32x2 %0, %1, %2, %0;" : "+l"(d) : "l"(a), "l"(b));
}
__device__ __forceinline__ float2 unpack2(u64 v) {
    float lo, hi;
    asm("mov.b64 {%0,%1}, %2;" : "=f"(lo), "=f"(hi) : "l"(v));
    return make_float2(lo, hi);
}

__global__ void proj_kernel(const float* __restrict__ x, const float* __restrict__ pos,
                            const float* __restrict__ Wq, const float* __restrict__ Wk,
                            const float* __restrict__ Wv, const float* __restrict__ pW1) {
    int i = blockIdx.x;
    int d = threadIdx.x;
    __shared__ float sx[DIM];
    sx[d] = x[i * DIM + d];
    __syncthreads();
    float q = 0.f, k = 0.f, v = 0.f;
#pragma unroll 8
    for (int e = 0; e < DIM; e++) {
        float xv = sx[e];
        q = fmaf(xv, Wq[e * DIM + d], q);
        k = fmaf(xv, Wk[e * DIM + d], k);
        v = fmaf(xv, Wv[e * DIM + d], v);
    }
    g_q[i * DIM + d] = q;
    g_k[i * DIM + d] = k;
    g_v[i * DIM + d] = v;
    float p0 = pos[i * 2 + 0], p1 = pos[i * 2 + 1];
    g_a[i * DIM + d] = p0 * pW1[d] + p1 * pW1[DIM + d];
}

__global__ void __launch_bounds__(256, 1)
pt_main(const float* __restrict__ pb1, const float* __restrict__ pW2,
        const float* __restrict__ pb2, const float* __restrict__ aW1,
        const float* __restrict__ ab1, const float* __restrict__ aW2,
        const float* __restrict__ ab2, float* __restrict__ out) {
    extern __shared__ float sm[];
    const int i = blockIdx.x;
    const int t = threadIdx.x;
    const int warp = t >> 5, lane = t & 31;
    const int jw = warp * 4;         // 8 warps * 4 j = 32 j per tile
    const int d_sm = t & 63;         // softmax channel per thread
    const int jmod = t >> 6;         // softmax j-residue per thread

    // ---- cooperative weight / bias loads into smem ----
    {
        const float4* s1 = (const float4*)aW1;
        float4* d1 = (float4*)(sm + OFF_AW1);
        for (int idx = t; idx < 4096; idx += 256) d1[idx] = s1[idx];
        const float4* s2 = (const float4*)aW2;
        float4* d2 = (float4*)(sm + OFF_AW2);
        for (int idx = t; idx < 4096; idx += 256) d2[idx] = s2[idx];
        const float4* s3 = (const float4*)pW2;
        float4* d3 = (float4*)(sm + OFF_PW2);
        for (int idx = t; idx < 1024; idx += 256) d3[idx] = s3[idx];
        sm[OFF_AB1 + t] = ab1[t];
        if (t < 64) {
            sm[OFF_QI + t] = g_q[i * DIM + t];
            sm[OFF_AI + t] = g_a[i * DIM + t];
            sm[OFF_AB2 + t] = ab2[t];
            sm[OFF_PB1 + t] = pb1[t];
            sm[OFF_PB2 + t] = pb2[t];
        }
    }

    float* sPh = sm + OFF_H;  // aliases H region (dead before GEMM1 writes H)

    float mrun = -1e30f, lrun = 0.f, arun = 0.f;

    for (int j0 = 0; j0 < NTOK; j0 += TJ) {
        __syncthreads();
        // ---- stage 1: ph[j][h] = relu(a_i - a_j + pb1) ----
        {
            int j = t >> 3;
            int h = (t & 7) * 8;
            const float* aj = g_a + (j0 + j) * DIM + h;
#pragma unroll
            for (int e = 0; e < 8; e++) {
                float val = sm[OFF_AI + h + e] - aj[e] + sm[OFF_PB1 + h + e];
                sPh[j * DIM + h + e] = fmaxf(val, 0.f);
            }
        }
        __syncthreads();
        // ---- stage 2: rpe = ph @ pW2 + pb2 ; u = q - k + rpe ; vv = v + rpe ----
        {
            u64 acc[4];
            u64 binit = *(const u64*)(sm + OFF_PB2 + 2 * lane);
#pragma unroll
            for (int jj = 0; jj < 4; jj++) acc[jj] = binit;
#pragma unroll 8
            for (int h = 0; h < 64; h++) {
                u64 w2 = *(const u64*)(sm + OFF_PW2 + h * 64 + 2 * lane);
#pragma unroll
                for (int jj = 0; jj < 4; jj++) {
                    u64 p = bcast2(sPh[(jw + jj) * DIM + h]);
                    fma2(acc[jj], p, w2);
                }
            }
            float qx = sm[OFF_QI + 2 * lane];
            float qy = sm[OFF_QI + 2 * lane + 1];
#pragma unroll
            for (int jj = 0; jj < 4; jj++) {
                int j = j0 + jw + jj;
                float2 rpe = unpack2(acc[jj]);
                float2 kv = *(const float2*)(g_k + j * DIM + 2 * lane);
                float2 vv = *(const float2*)(g_v + j * DIM + 2 * lane);
                float2 uo = make_float2(qx - kv.x + rpe.x, qy - kv.y + rpe.y);
                float2 vo = make_float2(vv.x + rpe.x, vv.y + rpe.y);
                *(float2*)(sm + OFF_U + (jw + jj) * DIM + 2 * lane) = uo;
                *(float2*)(sm + OFF_VV + (jw + jj) * DIM + 2 * lane) = vo;
            }
        }
        __syncthreads();
        // ---- stage 3: H = relu(U @ aW1 + ab1)  [32,64]@[64,256] ----
        {
            u64 acc[4][4];
#pragma unroll
            for (int m = 0; m < 4; m++) {
                u64 b = *(const u64*)(sm + OFF_AB1 + 64 * m + 2 * lane);
#pragma unroll
                for (int jj = 0; jj < 4; jj++) acc[jj][m] = b;
            }
#pragma unroll 4
            for (int d = 0; d < 64; d++) {
                u64 w[4];
#pragma unroll
                for (int m = 0; m < 4; m++)
                    w[m] = *(const u64*)(sm + OFF_AW1 + d * 256 + 64 * m + 2 * lane);
#pragma unroll
                for (int jj = 0; jj < 4; jj++) {
                    u64 u = bcast2(sm[OFF_U + (jw + jj) * DIM + d]);
#pragma unroll
                    for (int m = 0; m < 4; m++) fma2(acc[jj][m], u, w[m]);
                }
            }
#pragma unroll
            for (int jj = 0; jj < 4; jj++) {
#pragma unroll
                for (int m = 0; m < 4; m++) {
                    float2 h2 = unpack2(acc[jj][m]);
                    h2.x = fmaxf(h2.x, 0.f);
                    h2.y = fmaxf(h2.y, 0.f);
                    *(float2*)(sm + OFF_H + (jw + jj) * HATT + 64 * m + 2 * lane) = h2;
                }
            }
        }
        __syncthreads();
        // ---- stage 4: S = H @ aW2 + ab2  [32,256]@[256,64] ----
        {
            u64 acc[4];
            u64 binit = *(const u64*)(sm + OFF_AB2 + 2 * lane);
#pragma unroll
            for (int jj = 0; jj < 4; jj++) acc[jj] = binit;
#pragma unroll 4
            for (int c = 0; c < HATT; c += 4) {
                u64 w[4];
#pragma unroll
                for (int cc = 0; cc < 4; cc++)
                    w[cc] = *(const u64*)(sm + OFF_AW2 + (c + cc) * 64 + 2 * lane);
#pragma unroll
                for (int jj = 0; jj < 4; jj++) {
                    float4 hv = *(const float4*)(sm + OFF_H + (jw + jj) * HATT + c);
                    fma2(acc[jj], bcast2(hv.x), w[0]);
                    fma2(acc[jj], bcast2(hv.y), w[1]);
                    fma2(acc[jj], bcast2(hv.z), w[2]);
                    fma2(acc[jj], bcast2(hv.w), w[3]);
                }
            }
#pragma unroll
            for (int jj = 0; jj < 4; jj++)
                *(float2*)(sm + OFF_S + (jw + jj) * DIM + 2 * lane) = unpack2(acc[jj]);
        }
        __syncthreads();
        // ---- stage 5: per-channel online softmax (per-thread partials) ----
        {
#pragma unroll
            for (int jj = jmod; jj < TJ; jj += 4) {
                float s = sm[OFF_S + jj * DIM + d_sm];
                float vvv = sm[OFF_VV + jj * DIM + d_sm];
                float mnew = fmaxf(mrun, s);
                float sc = __expf(mrun - mnew);
                float e = __expf(s - mnew);
                lrun = lrun * sc + e;
                arun = arun * sc + e * vvv;
                mrun = mnew;
            }
        }
    }

    // ---- merge the 4 per-channel partials and write agg[i,:] ----
    __syncthreads();
    sm[OFF_RED + t] = mrun;
    sm[OFF_RED + 256 + t] = lrun;
    sm[OFF_RED + 512 + t] = arun;
    __syncthreads();
    if (t < 64) {
        float M = -1e30f;
#pragma unroll
        for (int r = 0; r < 4; r++) M = fmaxf(M, sm[OFF_RED + r * 64 + t]);
        float L = 0.f, A = 0.f;
#pragma unroll
        for (int r = 0; r < 4; r++) {
            float sc = __expf(sm[OFF_RED + r * 64 + t] - M);
            L += sm[OFF_RED + 256 + r * 64 + t] * sc;
            A += sm[OFF_RED + 512 + r * 64 + t] * sc;
        }
        out[i * DIM + t] = A / L;
    }
}

extern "C" void kernel_launch(void* const* d_in, const int* in_sizes, int n_in,
                              void* d_out, int out_size) {
    const float* x   = (const float*)d_in[0];
    const float* pos = (const float*)d_in[1];
    const float* Wq  = (const float*)d_in[2];
    const float* Wk  = (const float*)d_in[3];
    const float* Wv  = (const float*)d_in[4];
    const float* pW1 = (const float*)d_in[5];
    const float* pb1 = (const float*)d_in[6];
    const float* pW2 = (const float*)d_in[7];
    const float* pb2 = (const float*)d_in[8];
    const float* aW1 = (const float*)d_in[9];
    const float* ab1 = (const float*)d_in[10];
    const float* aW2 = (const float*)d_in[11];
    const float* ab2 = (const float*)d_in[12];
    float* out = (float*)d_out;

    cudaFuncSetAttribute(pt_main, cudaFuncAttributeMaxDynamicSharedMemorySize, SMEM_BYTES);

    proj_kernel<<<NTOK, DIM>>>(x, pos, Wq, Wk, Wv, pW1);
    pt_main<<<NTOK, 256, SMEM_BYTES>>>(pb1, pW2, pb2, aW1, ab1, aW2, ab2, out);
}

// round 8
// speedup vs baseline: 1.1980x; 1.1980x over previous
#include <cuda_runtime.h>

// PointTransformerLayer  B=1, N=1024, D=64, H_POS=64, H_ATTN=256
//
// proj_kernel: q,k,v = x@W*, a = pos@pW1  (precomputed to __device__ globals)
// pt_main: one CTA per query i, 8 warps; each warp owns 8 j-rows per 64-row
//   tile end-to-end on warp-private smem rows + registers:
//     ph  = relu((a_i+pb1) - a_j)          (PH aliases Hbuf rows)
//     rpe = ph @ pW2 + pb2 ; u = q_i - k_j + rpe (smem) ; vv = v_j + rpe (regs)
//     for g in {0,1}:  Hg = relu(u @ aW1[:,128g:128g+128] + ab1)  (warp-private smem)
//                      S += Hg @ aW2[128g:..., :]                 (regs, col=2*lane)
//     per-channel online softmax on S with vv, all in registers.
//   No __syncthreads() in the tile loop — warps are fully independent.
//   All GEMMs use packed fma.rn.f32x2 (2x fp32 rate on sm_103a).

#define NTOK 1024
#define DIM 64
#define TJ 64
#define RPW 8      // rows per warp per tile
#define HS 132     // Hbuf row stride in floats (128 cols + 4 pad)

// smem float offsets
#define OFF_AW1 0        // 64*256
#define OFF_AW2 16384    // 256*64
#define OFF_PW2 32768    // 64*64
#define OFF_HB  36864    // 64*HS = 8448  (PH aliases first 64 cols of each row)
#define OFF_U   45312    // 64*64
#define OFF_QI  49408    // 64
#define OFF_AIB 49472    // 64  (a_i + pb1)
#define OFF_AB1 49536    // 256
#define OFF_AB2 49792    // 64
#define OFF_PB2 49856    // 64
#define OFF_RED 49920    // 3*8*64
#define SMEM_FLOATS 51456
#define SMEM_BYTES (SMEM_FLOATS * 4)

__device__ float g_q[NTOK * DIM];
__device__ float g_k[NTOK * DIM];
__device__ float g_v[NTOK * DIM];
__device__ float g_a[NTOK * DIM];

typedef unsigned long long u64;

__device__ __forceinline__ u64 bcast2(float a) {
    u64 r; asm("mov.b64 %0, {%1,%1};" : "=l"(r) : "f"(a)); return r;
}
__device__ __forceinline__ void fma2(u64 &d, u64 a, u64 b) {
    asm("fma.rn.f32x2 %0, %1, %2, %0;" : "+l"(d) : "l"(a), "l"(b));
}
__device__ __forceinline__ float2 unpack2(u64 v) {
    float lo, hi;
    asm("mov.b64 {%0,%1}, %2;" : "=f"(lo), "=f"(hi) : "l"(v));
    return make_float2(lo, hi);
}

__global__ void proj_kernel(const float* __restrict__ x, const float* __restrict__ pos,
                            const float* __restrict__ Wq, const float* __restrict__ Wk,
                            const float* __restrict__ Wv, const float* __restrict__ pW1) {
    int i = blockIdx.x;
    int d = threadIdx.x;
    __shared__ float sx[DIM];
    sx[d] = x[i * DIM + d];
    __syncthreads();
    float q = 0.f, k = 0.f, v = 0.f;
#pragma unroll 8
    for (int e = 0; e < DIM; e++) {
        float xv = sx[e];
        q = fmaf(xv, Wq[e * DIM + d], q);
        k = fmaf(xv, Wk[e * DIM + d], k);
        v = fmaf(xv, Wv[e * DIM + d], v);
    }
    g_q[i * DIM + d] = q;
    g_k[i * DIM + d] = k;
    g_v[i * DIM + d] = v;
    float p0 = pos[i * 2 + 0], p1 = pos[i * 2 + 1];
    g_a[i * DIM + d] = p0 * pW1[d] + p1 * pW1[DIM + d];
}

__global__ void __launch_bounds__(256, 1)
pt_main(const float* __restrict__ pb1, const float* __restrict__ pW2,
        const float* __restrict__ pb2, const float* __restrict__ aW1,
        const float* __restrict__ ab1, const float* __restrict__ aW2,
        const float* __restrict__ ab2, float* __restrict__ out) {
    extern __shared__ float sm[];
    const int i = blockIdx.x;
    const int t = threadIdx.x;
    const int warp = t >> 5, lane = t & 31;
    const int rw = warp * RPW;

    // ---- cooperative loads ----
    {
        const float4* s1 = (const float4*)aW1;
        float4* d1 = (float4*)(sm + OFF_AW1);
        for (int idx = t; idx < 4096; idx += 256) d1[idx] = s1[idx];
        const float4* s2 = (const float4*)aW2;
        float4* d2 = (float4*)(sm + OFF_AW2);
        for (int idx = t; idx < 4096; idx += 256) d2[idx] = s2[idx];
        const float4* s3 = (const float4*)pW2;
        float4* d3 = (float4*)(sm + OFF_PW2);
        for (int idx = t; idx < 1024; idx += 256) d3[idx] = s3[idx];
        sm[OFF_AB1 + t] = ab1[t];
        if (t < 64) {
            sm[OFF_QI + t] = g_q[i * DIM + t];
            sm[OFF_AIB + t] = g_a[i * DIM + t] + pb1[t];
            sm[OFF_AB2 + t] = ab2[t];
            sm[OFF_PB2 + t] = pb2[t];
        }
    }
    __syncthreads();

    const float2 qv = *(const float2*)(sm + OFF_QI + 2 * lane);
    const u64 pb2p = *(const u64*)(sm + OFF_PB2 + 2 * lane);
    const u64 ab2p = *(const u64*)(sm + OFF_AB2 + 2 * lane);

    float2 Mr = make_float2(-1e30f, -1e30f);
    float2 Lr = make_float2(0.f, 0.f);
    float2 Ar = make_float2(0.f, 0.f);

    for (int j0 = 0; j0 < NTOK; j0 += TJ) {
        // ---- stage 1: PH[r][h] = relu(aib[h] - a_j[h]), warp-private rows ----
        {
            int r = lane >> 2;
            int hb = (lane & 3) * 16;
            const float4* aj = (const float4*)(g_a + (j0 + rw + r) * DIM + hb);
            const float4* aib = (const float4*)(sm + OFF_AIB + hb);
            float4* dst = (float4*)(sm + OFF_HB + (rw + r) * HS + hb);
#pragma unroll
            for (int e = 0; e < 4; e++) {
                float4 av = aj[e];
                float4 bv = aib[e];
                float4 o;
                o.x = fmaxf(bv.x - av.x, 0.f);
                o.y = fmaxf(bv.y - av.y, 0.f);
                o.z = fmaxf(bv.z - av.z, 0.f);
                o.w = fmaxf(bv.w - av.w, 0.f);
                dst[e] = o;
            }
        }
        __syncwarp();

        // ---- stage 2: rpe = PH @ pW2 + pb2 ; U = q - k + rpe ; vv = v + rpe ----
        float2 vvr[RPW];
        {
            u64 racc[RPW];
#pragma unroll
            for (int jj = 0; jj < RPW; jj++) racc[jj] = pb2p;
#pragma unroll 2
            for (int h = 0; h < 64; h += 2) {
                u64 w0 = *(const u64*)(sm + OFF_PW2 + h * 64 + 2 * lane);
                u64 w1 = *(const u64*)(sm + OFF_PW2 + (h + 1) * 64 + 2 * lane);
#pragma unroll
                for (int jj = 0; jj < RPW; jj++) {
                    float2 ph = *(const float2*)(sm + OFF_HB + (rw + jj) * HS + h);
                    fma2(racc[jj], bcast2(ph.x), w0);
                    fma2(racc[jj], bcast2(ph.y), w1);
                }
            }
#pragma unroll
            for (int jj = 0; jj < RPW; jj++) {
                int j = j0 + rw + jj;
                float2 rpe = unpack2(racc[jj]);
                float2 kv = *(const float2*)(g_k + j * DIM + 2 * lane);
                float2 vv = *(const float2*)(g_v + j * DIM + 2 * lane);
                float2 uo = make_float2(qv.x - kv.x + rpe.x, qv.y - kv.y + rpe.y);
                vvr[jj] = make_float2(vv.x + rpe.x, vv.y + rpe.y);
                *(float2*)(sm + OFF_U + (rw + jj) * DIM + 2 * lane) = uo;
            }
        }
        __syncwarp();

        // ---- stages 3+4 fused over two 128-col chunks of H_ATTN ----
        u64 acc2[RPW];
#pragma unroll
        for (int jj = 0; jj < RPW; jj++) acc2[jj] = ab2p;

        for (int g = 0; g < 2; g++) {
            // GEMM1 chunk: acc1[jj] = relu(U @ aW1[:, 128g + 4lane..+3] + ab1)
            u64 acc1[RPW][2];
            {
                u64 b0 = *(const u64*)(sm + OFF_AB1 + g * 128 + 4 * lane);
                u64 b1 = *(const u64*)(sm + OFF_AB1 + g * 128 + 4 * lane + 2);
#pragma unroll
                for (int jj = 0; jj < RPW; jj++) { acc1[jj][0] = b0; acc1[jj][1] = b1; }
            }
#pragma unroll 2
            for (int d = 0; d < 64; d += 2) {
                const float* wp = sm + OFF_AW1 + d * 256 + g * 128 + 4 * lane;
                u64 w0a = *(const u64*)(wp);
                u64 w0b = *(const u64*)(wp + 2);
                u64 w1a = *(const u64*)(wp + 256);
                u64 w1b = *(const u64*)(wp + 258);
#pragma unroll
                for (int jj = 0; jj < RPW; jj++) {
                    float2 up = *(const float2*)(sm + OFF_U + (rw + jj) * DIM + d);
                    u64 ux = bcast2(up.x);
                    u64 uy = bcast2(up.y);
                    fma2(acc1[jj][0], ux, w0a);
                    fma2(acc1[jj][1], ux, w0b);
                    fma2(acc1[jj][0], uy, w1a);
                    fma2(acc1[jj][1], uy, w1b);
                }
            }
            __syncwarp();
            // relu + store H chunk (warp-private rows), cols 4lane..4lane+3
#pragma unroll
            for (int jj = 0; jj < RPW; jj++) {
                float2 a0 = unpack2(acc1[jj][0]);
                float2 a1 = unpack2(acc1[jj][1]);
                float4 hv;
                hv.x = fmaxf(a0.x, 0.f);
                hv.y = fmaxf(a0.y, 0.f);
                hv.z = fmaxf(a1.x, 0.f);
                hv.w = fmaxf(a1.y, 0.f);
                *(float4*)(sm + OFF_HB + (rw + jj) * HS + 4 * lane) = hv;
            }
            __syncwarp();
            // GEMM2 chunk: acc2 += Hg @ aW2[128g+c, 2lane..2lane+1]
#pragma unroll 2
            for (int c = 0; c < 128; c += 4) {
                const float* wp = sm + OFF_AW2 + (g * 128 + c) * 64 + 2 * lane;
                u64 w0 = *(const u64*)(wp);
                u64 w1 = *(const u64*)(wp + 64);
                u64 w2 = *(const u64*)(wp + 128);
                u64 w3 = *(const u64*)(wp + 192);
#pragma unroll
                for (int jj = 0; jj < RPW; jj++) {
                    float4 hv = *(const float4*)(sm + OFF_HB + (rw + jj) * HS + c);
                    fma2(acc2[jj], bcast2(hv.x), w0);
                    fma2(acc2[jj], bcast2(hv.y), w1);
                    fma2(acc2[jj], bcast2(hv.z), w2);
                    fma2(acc2[jj], bcast2(hv.w), w3);
                }
            }
            __syncwarp();
        }

        // ---- stage 5: per-channel online softmax, all in registers ----
#pragma unroll
        for (int jj = 0; jj < RPW; jj++) {
            float2 s = unpack2(acc2[jj]);
            float mx = fmaxf(Mr.x, s.x);
            float my = fmaxf(Mr.y, s.y);
            float scx = __expf(Mr.x - mx);
            float scy = __expf(Mr.y - my);
            float ex = __expf(s.x - mx);
            float ey = __expf(s.y - my);
            Lr.x = Lr.x * scx + ex;
            Lr.y = Lr.y * scy + ey;
            Ar.x = Ar.x * scx + ex * vvr[jj].x;
            Ar.y = Ar.y * scy + ey * vvr[jj].y;
            Mr.x = mx;
            Mr.y = my;
        }
    }

    // ---- merge per-warp partials ----
    __syncthreads();
    sm[OFF_RED + warp * 64 + 2 * lane] = Mr.x;
    sm[OFF_RED + warp * 64 + 2 * lane + 1] = Mr.y;
    sm[OFF_RED + 512 + warp * 64 + 2 * lane] = Lr.x;
    sm[OFF_RED + 512 + warp * 64 + 2 * lane + 1] = Lr.y;
    sm[OFF_RED + 1024 + warp * 64 + 2 * lane] = Ar.x;
    sm[OFF_RED + 1024 + warp * 64 + 2 * lane + 1] = Ar.y;
    __syncthreads();
    if (t < 64) {
        float M = -1e30f;
#pragma unroll
        for (int w = 0; w < 8; w++) M = fmaxf(M, sm[OFF_RED + w * 64 + t]);
        float L = 0.f, A = 0.f;
#pragma unroll
        for (int w = 0; w < 8; w++) {
            float sc = __expf(sm[OFF_RED + w * 64 + t] - M);
            L += sm[OFF_RED + 512 + w * 64 + t] * sc;
            A += sm[OFF_RED + 1024 + w * 64 + t] * sc;
        }
        out[i * DIM + t] = A / L;
    }
}

extern "C" void kernel_launch(void* const* d_in, const int* in_sizes, int n_in,
                              void* d_out, int out_size) {
    const float* x   = (const float*)d_in[0];
    const float* pos = (const float*)d_in[1];
    const float* Wq  = (const float*)d_in[2];
    const float* Wk  = (const float*)d_in[3];
    const float* Wv  = (const float*)d_in[4];
    const float* pW1 = (const float*)d_in[5];
    const float* pb1 = (const float*)d_in[6];
    const float* pW2 = (const float*)d_in[7];
    const float* pb2 = (const float*)d_in[8];
    const float* aW1 = (const float*)d_in[9];
    const float* ab1 = (const float*)d_in[10];
    const float* aW2 = (const float*)d_in[11];
    const float* ab2 = (const float*)d_in[12];
    float* out = (float*)d_out;

    cudaFuncSetAttribute(pt_main, cudaFuncAttributeMaxDynamicSharedMemorySize, SMEM_BYTES);

    proj_kernel<<<NTOK, DIM>>>(x, pos, Wq, Wk, Wv, pW1);
    pt_main<<<NTOK, 256, SMEM_BYTES>>>(pb1, pW2, pb2, aW1, ab1, aW2, ab2, out);
}